// round 7
// baseline (speedup 1.0000x reference)
#include <cuda_runtime.h>
#include <cstdint>

// RadianceFieldTT: 8-level quantized tensor-train radiance field sampler.
//
// R6 design: R4 (owner-computes, balanced slices, non-duplicated v in smem) +
//   - FOUR samples in flight per warp (16 independent FFMA2 chains) to cover
//     LDS->FFMA latency at the fixed 2-warps/SMSP occupancy.
//   - lane owns output cols {2*lane, 2*lane+1}: weight reload = 64 LDG.64
//     (half the instructions of 128 LDG.32), v writeback = 1 STS.64.

#define THREADS 256
#define RANK    64
#define VSTRIDE 68    // floats per v row: 64 + 4 pad (272 B, 16B-aligned)

// ---- shared memory layout (bytes) ----
#define SM_V      0                          // 256 * 68 * 4 = 69632
#define SM_PP     (256 * VSTRIDE * 4)        // 69632: P' float4[64] = 1024
#define SM_LIST   (SM_PP + 1024)             // 70656: uint8 list[7][256] = 1792
#define SM_CNT    (SM_LIST + 1792)           // 72448: int cnt[7][8] = 224
#define SM_OFF    (SM_CNT + 224)             // 72672: int off[7][9] = 252
#define SM_BYTES  (SM_OFF + 256)             // 72928 B total

typedef unsigned long long u64;

__device__ __forceinline__ u64 pk2(float lo, float hi) {
    u64 r; asm("mov.b64 %0, {%1, %2};" : "=l"(r) : "f"(lo), "f"(hi)); return r;
}
__device__ __forceinline__ void upk2(u64 v, float& lo, float& hi) {
    asm("mov.b64 {%0, %1}, %2;" : "=f"(lo), "=f"(hi) : "l"(v));
}
__device__ __forceinline__ u64 ffma2(u64 a, u64 b, u64 c) {
    u64 d; asm("fma.rn.f32x2 %0, %1, %2, %3;" : "=l"(d) : "l"(a), "l"(b), "l"(c)); return d;
}
__device__ __forceinline__ u64 add2(u64 a, u64 b) {
    u64 d; asm("add.rn.f32x2 %0, %1, %2;" : "=l"(d) : "l"(a), "l"(b)); return d;
}

// Process NS samples (same weight matrix) from lst[k..k+NS).
// wa[q] = {W[2q][c0], W[2q+1][c0]},  wb[q] = {W[2q][c1], W[2q+1][c1]},
// c0 = 2*lane, c1 = 2*lane+1.
template <int NS>
__device__ __forceinline__ void do_samples(const uint8_t* __restrict__ lst, int k,
                                           float* __restrict__ v2f,
                                           const u64* __restrict__ wa,
                                           const u64* __restrict__ wb, int lane)
{
    const ulonglong2* vr[NS];
    int idx[NS];
#pragma unroll
    for (int s = 0; s < NS; ++s) {
        idx[s] = lst[k + s];
        vr[s] = (const ulonglong2*)(v2f + (size_t)idx[s] * VSTRIDE);
    }
    u64 a0[NS], a1[NS], b0[NS], b1[NS];
#pragma unroll
    for (int s = 0; s < NS; ++s) { a0[s] = a1[s] = b0[s] = b1[s] = 0ull; }

#pragma unroll
    for (int q = 0; q < 16; ++q) {
#pragma unroll
        for (int s = 0; s < NS; ++s) {
            const ulonglong2 p = vr[s][q];      // uniform LDS.128 (broadcast)
            a0[s] = ffma2(wa[2 * q + 0], p.x, a0[s]);
            b0[s] = ffma2(wb[2 * q + 0], p.x, b0[s]);
            a1[s] = ffma2(wa[2 * q + 1], p.y, a1[s]);
            b1[s] = ffma2(wb[2 * q + 1], p.y, b1[s]);
        }
    }
#pragma unroll
    for (int s = 0; s < NS; ++s) {
        float x0, x1, y0, y1;
        upk2(add2(a0[s], a1[s]), x0, x1);
        upk2(add2(b0[s], b1[s]), y0, y1);
        // one coalesced STS.64: cols {2*lane, 2*lane+1}
        *(u64*)(v2f + (size_t)idx[s] * VSTRIDE + 2 * lane) = pk2(x0 + x1, y0 + y1);
    }
}

__global__ __launch_bounds__(THREADS, 1)
void rftt_kernel(const float* __restrict__ coords,
                 const float* __restrict__ viewdirs,
                 const float* __restrict__ core0,
                 const float* __restrict__ cores,
                 const float* __restrict__ payload,
                 float* __restrict__ out)
{
    extern __shared__ char smb[];
    float*   v2f  = (float*)(smb + SM_V);
    float*   pp   = (float*)(smb + SM_PP);
    uint8_t* list = (uint8_t*)(smb + SM_LIST);
    int*     cnt  = (int*)(smb + SM_CNT);
    int*     off  = (int*)(smb + SM_OFF);

    const int tid  = threadIdx.x;
    const int warp = tid >> 5;
    const int lane = tid & 31;
    const int b    = blockIdx.x;
    const int n    = b * THREADS + tid;
    const int ntot = gridDim.x * THREADS;

    // ---- per-sample digits + inside mask ----
    const float cx = coords[3 * n + 0];
    const float cy = coords[3 * n + 1];
    const float cz = coords[3 * n + 2];
    const float msk = (fabsf(cx) <= 1.f && fabsf(cy) <= 1.f && fabsf(cz) <= 1.f) ? 1.f : 0.f;
    const int ix = min(255, max(0, (int)floorf((cx * 0.5f + 0.5f) * 256.f)));
    const int iy = min(255, max(0, (int)floorf((cy * 0.5f + 0.5f) * 256.f)));
    const int iz = min(255, max(0, (int)floorf((cz * 0.5f + 0.5f) * 256.f)));
    unsigned int dig = 0;
#pragma unroll
    for (int l = 0; l < 8; ++l) {
        const int s = 7 - l;
        const unsigned int d = (((ix >> s) & 1) << 2) | (((iy >> s) & 1) << 1) | ((iz >> s) & 1);
        dig |= d << (4 * l);
    }

    // ---- per-CTA precontracted payload P'[r] (CTA == one batch row b) ----
    if (tid < RANK) {
        const float* vd = viewdirs + 3 * b;
        const float dx = vd[0], dy = vd[1], dz = vd[2];
        float shv[9];
        shv[0] = 0.28209479177387814f;
        shv[1] = -0.4886025119029199f * dy;
        shv[2] =  0.4886025119029199f * dz;
        shv[3] = -0.4886025119029199f * dx;
        shv[4] =  1.0925484305920792f * dx * dy;
        shv[5] = -1.0925484305920792f * dy * dz;
        shv[6] =  0.31539156525252005f * (2.f * dz * dz - dx * dx - dy * dy);
        shv[7] = -1.0925484305920792f * dx * dz;
        shv[8] =  0.5462742152960396f * (dx * dx - dy * dy);
        const float* pr = payload + tid * 28;
        float s0 = 0.f, s1 = 0.f, s2 = 0.f;
#pragma unroll
        for (int j = 0; j < 9; ++j) {
            s0 = fmaf(pr[j],      shv[j], s0);
            s1 = fmaf(pr[9 + j],  shv[j], s1);
            s2 = fmaf(pr[18 + j], shv[j], s2);
        }
        *(float4*)(pp + 4 * tid) = make_float4(s0, s1, s2, pr[27]);
    }

    // ---- init v row: v2f[tid][:] = core0[digit0] ----
    {
        const float4* src = (const float4*)(core0 + (dig & 7) * RANK);
        float4* dst = (float4*)(v2f + (size_t)tid * VSTRIDE);
#pragma unroll
        for (int q = 0; q < 16; ++q) dst[q] = src[q];
    }

    // ---- counting sort: per-level digit lists (bucket-major) ----
    if (tid < 56) cnt[tid] = 0;
    __syncthreads();
    int rank7[7];
#pragma unroll
    for (int l = 1; l < 8; ++l)
        rank7[l - 1] = atomicAdd(&cnt[(l - 1) * 8 + ((dig >> (4 * l)) & 7)], 1);
    __syncthreads();
    if (tid < 7) {
        int s = 0;
#pragma unroll
        for (int d = 0; d < 8; ++d) { off[tid * 9 + d] = s; s += cnt[tid * 8 + d]; }
        off[tid * 9 + 8] = 256;
    }
    __syncthreads();
#pragma unroll
    for (int l = 1; l < 8; ++l) {
        const int d = (dig >> (4 * l)) & 7;
        list[(l - 1) * 256 + off[(l - 1) * 9 + d] + rank7[l - 1]] = (uint8_t)tid;
    }
    __syncthreads();

    // ---- TT chain: levels 1..7 ----
#pragma unroll 1
    for (int l = 1; l < 8; ++l) {
        const int* offL = off + (l - 1) * 9;
        const uint8_t* lst = list + (l - 1) * 256;
        const float* wlev = cores + (size_t)(l - 1) * 32768;   // [r][m][c]: r*512 + m*64 + c

        const int k0 = warp * 32;
        const int k1 = k0 + 32;

        int d = 0;
        while (offL[d + 1] <= k0) ++d;

        u64 wa[32], wb[32];
        {
            const float* wd = wlev + d * 64 + 2 * lane;
#pragma unroll
            for (int q = 0; q < 32; ++q) {
                const u64 t0 = *(const u64*)(wd + (2 * q) * 512);      // LDG.64 coalesced
                const u64 t1 = *(const u64*)(wd + (2 * q + 1) * 512);
                float c00, c10, c01, c11;
                upk2(t0, c00, c10);    // {W[2q][c0], W[2q][c1]}
                upk2(t1, c01, c11);    // {W[2q+1][c0], W[2q+1][c1]}
                wa[q] = pk2(c00, c01);
                wb[q] = pk2(c10, c11);
            }
        }

        int k = k0;
#pragma unroll 1
        while (k < k1) {
            if (k >= offL[d + 1]) {            // crossed into next non-empty bucket
                do { ++d; } while (k >= offL[d + 1]);
                const float* wd = wlev + d * 64 + 2 * lane;
#pragma unroll
                for (int q = 0; q < 32; ++q) {
                    const u64 t0 = *(const u64*)(wd + (2 * q) * 512);
                    const u64 t1 = *(const u64*)(wd + (2 * q + 1) * 512);
                    float c00, c10, c01, c11;
                    upk2(t0, c00, c10);
                    upk2(t1, c01, c11);
                    wa[q] = pk2(c00, c01);
                    wb[q] = pk2(c10, c11);
                }
            }
            const int run_end = min(k1, offL[d + 1]);

#pragma unroll 1
            for (; k + 3 < run_end; k += 4)
                do_samples<4>(lst, k, v2f, wa, wb, lane);
            if (k + 1 < run_end) {
                do_samples<2>(lst, k, v2f, wa, wb, lane);
                k += 2;
            }
            if (k < run_end) {
                do_samples<1>(lst, k, v2f, wa, wb, lane);
                ++k;
            }
        }
        __syncthreads();
    }

    // ---- epilogue: thread t -> sample t: out = v @ P' (64x4), mask, store ----
    float o0 = 0.f, o1 = 0.f, o2 = 0.f, o3 = 0.f;
    {
        const float4* vrow = (const float4*)(v2f + (size_t)tid * VSTRIDE);
#pragma unroll
        for (int q = 0; q < 16; ++q) {
            const float4 t = vrow[q];
            const float4 p0 = *(const float4*)(pp + 4 * (4 * q + 0));
            const float4 p1 = *(const float4*)(pp + 4 * (4 * q + 1));
            const float4 p2 = *(const float4*)(pp + 4 * (4 * q + 2));
            const float4 p3 = *(const float4*)(pp + 4 * (4 * q + 3));
            o0 = fmaf(t.x, p0.x, o0); o1 = fmaf(t.x, p0.y, o1);
            o2 = fmaf(t.x, p0.z, o2); o3 = fmaf(t.x, p0.w, o3);
            o0 = fmaf(t.y, p1.x, o0); o1 = fmaf(t.y, p1.y, o1);
            o2 = fmaf(t.y, p1.z, o2); o3 = fmaf(t.y, p1.w, o3);
            o0 = fmaf(t.z, p2.x, o0); o1 = fmaf(t.z, p2.y, o1);
            o2 = fmaf(t.z, p2.z, o2); o3 = fmaf(t.z, p2.w, o3);
            o0 = fmaf(t.w, p3.x, o0); o1 = fmaf(t.w, p3.y, o1);
            o2 = fmaf(t.w, p3.z, o2); o3 = fmaf(t.w, p3.w, o3);
        }
    }
    out[3 * n + 0] = o0 * msk;
    out[3 * n + 1] = o1 * msk;
    out[3 * n + 2] = o2 * msk;
    out[3 * ntot + n] = o3 * msk;   // sigma block after rgb block
}

extern "C" void kernel_launch(void* const* d_in, const int* in_sizes, int n_in,
                              void* d_out, int out_size) {
    const float* coords   = (const float*)d_in[0];  // (B,R,3)
    const float* viewdirs = (const float*)d_in[1];  // (B,3)
    const float* core0    = (const float*)d_in[2];  // (1,8,64)
    const float* cores    = (const float*)d_in[3];  // (7,64,8,64)
    const float* payload  = (const float*)d_in[4];  // (64,28)

    const int B = in_sizes[1] / 3;   // 1024 (R = 256 = THREADS)

    cudaFuncSetAttribute(rftt_kernel, cudaFuncAttributeMaxDynamicSharedMemorySize, SM_BYTES);
    rftt_kernel<<<B, THREADS, SM_BYTES>>>(coords, viewdirs, core0, cores, payload, (float*)d_out);
}

// round 8
// speedup vs baseline: 1.0592x; 1.0592x over previous
#include <cuda_runtime.h>
#include <cstdint>

// RadianceFieldTT: 8-level quantized tensor-train radiance field sampler.
//
// R7 design: pass-count reduction via associativity.
//   - Precompute kernel builds C_p[da*8+db] = W_{2p+1}(da) @ W_{2p+2}(db) for
//     the 3 level-pairs (3*64 matrices, 3 MB __device__ table, L2-resident).
//   - Main kernel runs only THREE matvec passes (64-bucket digit-pair sort,
//     same owner-computes balanced-slice inner loop as R4/R6).
//   - Level 7 folds into the payload: out = v6 @ (W7(d7) @ P'); the 8 tiny
//     WP[d] = W7(d) @ P' (64x4) matrices are computed per-CTA in smem.

#define THREADS 256
#define RANK    64
#define VSTRIDE 68    // floats per v row: 64 + 4 pad (272 B, 16B-aligned)

// ---- shared memory layout (bytes) ----
#define SM_V      0                          // 256 * 68 * 4 = 69632
#define SM_PP     69632                      // P' float4[64] = 1024
#define SM_WP     70656                      // WP[8][260] floats = 8320 (pad stride 260)
#define SM_LIST   78976                      // uint8 list[3][256] = 768
#define SM_CNT    79744                      // int cnt[3][64] = 768
#define SM_OFF    80512                      // int off[3][65] = 780
#define SM_BYTES  81408

typedef unsigned long long u64;

__device__ float g_w[3 * 64 * 4096];   // combined pair-level weight table (3 MB)

__device__ __forceinline__ u64 pk2(float lo, float hi) {
    u64 r; asm("mov.b64 %0, {%1, %2};" : "=l"(r) : "f"(lo), "f"(hi)); return r;
}
__device__ __forceinline__ void upk2(u64 v, float& lo, float& hi) {
    asm("mov.b64 {%0, %1}, %2;" : "=f"(lo), "=f"(hi) : "l"(v));
}
__device__ __forceinline__ u64 ffma2(u64 a, u64 b, u64 c) {
    u64 d; asm("fma.rn.f32x2 %0, %1, %2, %3;" : "=l"(d) : "l"(a), "l"(b), "l"(c)); return d;
}
__device__ __forceinline__ u64 add2(u64 a, u64 b) {
    u64 d; asm("add.rn.f32x2 %0, %1, %2;" : "=l"(d) : "l"(a), "l"(b)); return d;
}

// ---- precompute: C = A @ B for one (pair, da, db) combo ----
// A[r][k] = cores[2p][r][da][k],  B[k][s] = cores[2p+1][k][db][s]
// Output layout: g_w[combo*4096 + r*64 + s]  (r contiguous-64 rows)
__global__ void __launch_bounds__(128) precombine_kernel(const float* __restrict__ cores)
{
    __shared__ float sA[4096];
    __shared__ float sB[4096];
    const int combo = blockIdx.x;          // 0..191: p*64 + da*8 + db
    const int p  = combo >> 6;
    const int da = (combo >> 3) & 7;
    const int db = combo & 7;
    const int t = threadIdx.x;

    const float* A  = cores + (size_t)(2 * p) * 32768 + da * 64;       // + r*512 + k
    const float* Bm = cores + (size_t)(2 * p + 1) * 32768 + db * 64;   // + k*512 + s
    for (int i = t; i < 1024; i += 128) {
        const int row = i >> 4, c4 = (i & 15) * 4;
        *(float4*)(sA + row * 64 + c4) = *(const float4*)(A  + row * 512 + c4);
        *(float4*)(sB + row * 64 + c4) = *(const float4*)(Bm + row * 512 + c4);
    }
    __syncthreads();

    const int r  = t >> 1;
    const int s0 = (t & 1) * 32;
    float acc[32];
#pragma unroll
    for (int i = 0; i < 32; ++i) acc[i] = 0.f;
#pragma unroll 4
    for (int k = 0; k < 64; ++k) {
        const float a = sA[r * 64 + k];
#pragma unroll
        for (int i = 0; i < 32; ++i) acc[i] = fmaf(a, sB[k * 64 + s0 + i], acc[i]);
    }
    float* dst = g_w + (size_t)combo * 4096 + r * 64 + s0;
#pragma unroll
    for (int i = 0; i < 32; ++i) dst[i] = acc[i];
}

// Process NS samples (same weight matrix) from lst[k..k+NS).
template <int NS>
__device__ __forceinline__ void do_samples(const uint8_t* __restrict__ lst, int k,
                                           float* __restrict__ v2f,
                                           const u64* __restrict__ wa,
                                           const u64* __restrict__ wb, int lane)
{
    const ulonglong2* vr[NS];
    int idx[NS];
#pragma unroll
    for (int s = 0; s < NS; ++s) {
        idx[s] = lst[k + s];
        vr[s] = (const ulonglong2*)(v2f + (size_t)idx[s] * VSTRIDE);
    }
    u64 a0[NS], a1[NS], b0[NS], b1[NS];
#pragma unroll
    for (int s = 0; s < NS; ++s) { a0[s] = a1[s] = b0[s] = b1[s] = 0ull; }

#pragma unroll
    for (int q = 0; q < 16; ++q) {
#pragma unroll
        for (int s = 0; s < NS; ++s) {
            const ulonglong2 p = vr[s][q];      // uniform LDS.128 (broadcast)
            a0[s] = ffma2(wa[2 * q + 0], p.x, a0[s]);
            b0[s] = ffma2(wb[2 * q + 0], p.x, b0[s]);
            a1[s] = ffma2(wa[2 * q + 1], p.y, a1[s]);
            b1[s] = ffma2(wb[2 * q + 1], p.y, b1[s]);
        }
    }
#pragma unroll
    for (int s = 0; s < NS; ++s) {
        float x0, x1, y0, y1;
        upk2(add2(a0[s], a1[s]), x0, x1);
        upk2(add2(b0[s], b1[s]), y0, y1);
        *(u64*)(v2f + (size_t)idx[s] * VSTRIDE + 2 * lane) = pk2(x0 + x1, y0 + y1);
    }
}

__global__ __launch_bounds__(THREADS, 1)
void rftt_kernel(const float* __restrict__ coords,
                 const float* __restrict__ viewdirs,
                 const float* __restrict__ core0,
                 const float* __restrict__ cores,
                 const float* __restrict__ payload,
                 float* __restrict__ out)
{
    extern __shared__ char smb[];
    float*   v2f  = (float*)(smb + SM_V);
    float*   pp   = (float*)(smb + SM_PP);
    float*   wp   = (float*)(smb + SM_WP);     // WP[d][r][j]: d*260 + r*4 + j
    uint8_t* list = (uint8_t*)(smb + SM_LIST);
    int*     cnt  = (int*)(smb + SM_CNT);
    int*     off  = (int*)(smb + SM_OFF);

    const int tid  = threadIdx.x;
    const int warp = tid >> 5;
    const int lane = tid & 31;
    const int b    = blockIdx.x;
    const int n    = b * THREADS + tid;
    const int ntot = gridDim.x * THREADS;

    // ---- per-sample digits + inside mask ----
    const float cx = coords[3 * n + 0];
    const float cy = coords[3 * n + 1];
    const float cz = coords[3 * n + 2];
    const float msk = (fabsf(cx) <= 1.f && fabsf(cy) <= 1.f && fabsf(cz) <= 1.f) ? 1.f : 0.f;
    const int ix = min(255, max(0, (int)floorf((cx * 0.5f + 0.5f) * 256.f)));
    const int iy = min(255, max(0, (int)floorf((cy * 0.5f + 0.5f) * 256.f)));
    const int iz = min(255, max(0, (int)floorf((cz * 0.5f + 0.5f) * 256.f)));
    unsigned int dig = 0;
#pragma unroll
    for (int l = 0; l < 8; ++l) {
        const int s = 7 - l;
        const unsigned int d = (((ix >> s) & 1) << 2) | (((iy >> s) & 1) << 1) | ((iz >> s) & 1);
        dig |= d << (4 * l);
    }
    const int d7 = (dig >> 28) & 7;

    // ---- per-CTA precontracted payload P'[r] (CTA == one batch row b) ----
    if (tid < RANK) {
        const float* vd = viewdirs + 3 * b;
        const float dx = vd[0], dy = vd[1], dz = vd[2];
        float shv[9];
        shv[0] = 0.28209479177387814f;
        shv[1] = -0.4886025119029199f * dy;
        shv[2] =  0.4886025119029199f * dz;
        shv[3] = -0.4886025119029199f * dx;
        shv[4] =  1.0925484305920792f * dx * dy;
        shv[5] = -1.0925484305920792f * dy * dz;
        shv[6] =  0.31539156525252005f * (2.f * dz * dz - dx * dx - dy * dy);
        shv[7] = -1.0925484305920792f * dx * dz;
        shv[8] =  0.5462742152960396f * (dx * dx - dy * dy);
        const float* pr = payload + tid * 28;
        float s0 = 0.f, s1 = 0.f, s2 = 0.f;
#pragma unroll
        for (int j = 0; j < 9; ++j) {
            s0 = fmaf(pr[j],      shv[j], s0);
            s1 = fmaf(pr[9 + j],  shv[j], s1);
            s2 = fmaf(pr[18 + j], shv[j], s2);
        }
        *(float4*)(pp + 4 * tid) = make_float4(s0, s1, s2, pr[27]);
    }

    // ---- init v row: v2f[tid][:] = core0[digit0] ----
    {
        const float4* src = (const float4*)(core0 + (dig & 7) * RANK);
        float4* dst = (float4*)(v2f + (size_t)tid * VSTRIDE);
#pragma unroll
        for (int q = 0; q < 16; ++q) dst[q] = src[q];
    }

    // ---- counting sort: 3 digit-pair lists (64 buckets each) ----
    if (tid < 192) cnt[tid] = 0;
    __syncthreads();
    int dp[3], rank3[3];
#pragma unroll
    for (int p = 0; p < 3; ++p) {
        dp[p] = (int)(((dig >> (4 * (2 * p + 1))) & 7) * 8 + ((dig >> (4 * (2 * p + 2))) & 7));
        rank3[p] = atomicAdd(&cnt[p * 64 + dp[p]], 1);
    }
    __syncthreads();
    if (tid < 3) {
        int s = 0;
#pragma unroll 1
        for (int d = 0; d < 64; ++d) { off[tid * 65 + d] = s; s += cnt[tid * 64 + d]; }
        off[tid * 65 + 64] = 256;
    }
    __syncthreads();
#pragma unroll
    for (int p = 0; p < 3; ++p)
        list[p * 256 + off[p * 65 + dp[p]] + rank3[p]] = (uint8_t)tid;
    __syncthreads();

    // ---- TT chain: 3 merged passes over the pair table ----
#pragma unroll 1
    for (int p = 0; p < 3; ++p) {
        const int* offL = off + p * 65;
        const uint8_t* lst = list + p * 256;
        const float* wlev = g_w + (size_t)p * 64 * 4096;   // [combo][r][c]: combo*4096 + r*64 + c

        const int k0 = warp * 32;
        const int k1 = k0 + 32;

        int d = 0;
        while (offL[d + 1] <= k0) ++d;

        u64 wa[32], wb[32];    // lane's cols {2*lane, 2*lane+1}, paired along r
        {
            const float* wd = wlev + (size_t)d * 4096 + 2 * lane;
#pragma unroll
            for (int q = 0; q < 32; ++q) {
                const u64 t0 = *(const u64*)(wd + (2 * q) * 64);       // LDG.64 coalesced
                const u64 t1 = *(const u64*)(wd + (2 * q + 1) * 64);
                float c00, c10, c01, c11;
                upk2(t0, c00, c10);
                upk2(t1, c01, c11);
                wa[q] = pk2(c00, c01);
                wb[q] = pk2(c10, c11);
            }
        }

        int k = k0;
#pragma unroll 1
        while (k < k1) {
            if (k >= offL[d + 1]) {            // crossed into next non-empty bucket
                do { ++d; } while (k >= offL[d + 1]);
                const float* wd = wlev + (size_t)d * 4096 + 2 * lane;
#pragma unroll
                for (int q = 0; q < 32; ++q) {
                    const u64 t0 = *(const u64*)(wd + (2 * q) * 64);
                    const u64 t1 = *(const u64*)(wd + (2 * q + 1) * 64);
                    float c00, c10, c01, c11;
                    upk2(t0, c00, c10);
                    upk2(t1, c01, c11);
                    wa[q] = pk2(c00, c01);
                    wb[q] = pk2(c10, c11);
                }
            }
            const int run_end = min(k1, offL[d + 1]);

#pragma unroll 1
            for (; k + 3 < run_end; k += 4)
                do_samples<4>(lst, k, v2f, wa, wb, lane);
            if (k + 1 < run_end) {
                do_samples<2>(lst, k, v2f, wa, wb, lane);
                k += 2;
            }
            if (k < run_end) {
                do_samples<1>(lst, k, v2f, wa, wb, lane);
                ++k;
            }
        }
        __syncthreads();
    }

    // ---- per-CTA WP[d] = W7(d) @ P'  (8 x 64 x 4) ----
#pragma unroll
    for (int i = 0; i < 2; ++i) {
        const int idx = tid + i * 256;          // 0..511: d = idx>>6, r = idx&63
        const int d = idx >> 6, r = idx & 63;
        const float* src = cores + (size_t)6 * 32768 + r * 512 + d * 64;  // W7[r][d][s], s contiguous
        float a0 = 0.f, a1 = 0.f, a2 = 0.f, a3 = 0.f;
#pragma unroll 4
        for (int s4 = 0; s4 < 16; ++s4) {
            const float4 w4 = *(const float4*)(src + 4 * s4);
            const float4 p0 = *(const float4*)(pp + 4 * (4 * s4 + 0));
            const float4 p1 = *(const float4*)(pp + 4 * (4 * s4 + 1));
            const float4 p2 = *(const float4*)(pp + 4 * (4 * s4 + 2));
            const float4 p3 = *(const float4*)(pp + 4 * (4 * s4 + 3));
            a0 = fmaf(w4.x, p0.x, a0); a1 = fmaf(w4.x, p0.y, a1);
            a2 = fmaf(w4.x, p0.z, a2); a3 = fmaf(w4.x, p0.w, a3);
            a0 = fmaf(w4.y, p1.x, a0); a1 = fmaf(w4.y, p1.y, a1);
            a2 = fmaf(w4.y, p1.z, a2); a3 = fmaf(w4.y, p1.w, a3);
            a0 = fmaf(w4.z, p2.x, a0); a1 = fmaf(w4.z, p2.y, a1);
            a2 = fmaf(w4.z, p2.z, a2); a3 = fmaf(w4.z, p2.w, a3);
            a0 = fmaf(w4.w, p3.x, a0); a1 = fmaf(w4.w, p3.y, a1);
            a2 = fmaf(w4.w, p3.z, a2); a3 = fmaf(w4.w, p3.w, a3);
        }
        *(float4*)(wp + d * 260 + r * 4) = make_float4(a0, a1, a2, a3);
    }
    __syncthreads();

    // ---- epilogue: thread t -> sample t: out = v6 @ WP[d7], mask, store ----
    float o0 = 0.f, o1 = 0.f, o2 = 0.f, o3 = 0.f;
    {
        const float4* vrow = (const float4*)(v2f + (size_t)tid * VSTRIDE);
        const float* wrow = wp + d7 * 260;
#pragma unroll
        for (int q = 0; q < 16; ++q) {
            const float4 t = vrow[q];
            const float4 p0 = *(const float4*)(wrow + 4 * (4 * q + 0));
            const float4 p1 = *(const float4*)(wrow + 4 * (4 * q + 1));
            const float4 p2 = *(const float4*)(wrow + 4 * (4 * q + 2));
            const float4 p3 = *(const float4*)(wrow + 4 * (4 * q + 3));
            o0 = fmaf(t.x, p0.x, o0); o1 = fmaf(t.x, p0.y, o1);
            o2 = fmaf(t.x, p0.z, o2); o3 = fmaf(t.x, p0.w, o3);
            o0 = fmaf(t.y, p1.x, o0); o1 = fmaf(t.y, p1.y, o1);
            o2 = fmaf(t.y, p1.z, o2); o3 = fmaf(t.y, p1.w, o3);
            o0 = fmaf(t.z, p2.x, o0); o1 = fmaf(t.z, p2.y, o1);
            o2 = fmaf(t.z, p2.z, o2); o3 = fmaf(t.z, p2.w, o3);
            o0 = fmaf(t.w, p3.x, o0); o1 = fmaf(t.w, p3.y, o1);
            o2 = fmaf(t.w, p3.z, o2); o3 = fmaf(t.w, p3.w, o3);
        }
    }
    out[3 * n + 0] = o0 * msk;
    out[3 * n + 1] = o1 * msk;
    out[3 * n + 2] = o2 * msk;
    out[3 * ntot + n] = o3 * msk;   // sigma block after rgb block
}

extern "C" void kernel_launch(void* const* d_in, const int* in_sizes, int n_in,
                              void* d_out, int out_size) {
    const float* coords   = (const float*)d_in[0];  // (B,R,3)
    const float* viewdirs = (const float*)d_in[1];  // (B,3)
    const float* core0    = (const float*)d_in[2];  // (1,8,64)
    const float* cores    = (const float*)d_in[3];  // (7,64,8,64)
    const float* payload  = (const float*)d_in[4];  // (64,28)

    const int B = in_sizes[1] / 3;   // 1024 (R = 256 = THREADS)

    precombine_kernel<<<192, 128>>>(cores);

    cudaFuncSetAttribute(rftt_kernel, cudaFuncAttributeMaxDynamicSharedMemorySize, SM_BYTES);
    rftt_kernel<<<B, THREADS, SM_BYTES>>>(coords, viewdirs, core0, cores, payload, (float*)d_out);
}

// round 10
// speedup vs baseline: 1.3807x; 1.3036x over previous
#include <cuda_runtime.h>
#include <cstdint>

// RadianceFieldTT — R9: globally-bucketed streaming passes (R8 + gather fix).
//
//  1) k_zero/k_keys/k_scan/k_scatter: global counting sort of all N samples by
//     digit-pair key for each of the 3 merged passes (runs ~4096 long).
//  2) precombine: C_p[da*8+db] = W_{2p+1}(da) @ W_{2p+2}(db), written directly
//     in the per-lane packed register layout (ulonglong2 {wa_q, wb_q}).
//  3) k_pass x3: tile of 128 perm-ordered samples -> gather v rows to smem ->
//     each warp (weights in regs, ~1 load per pass) streams 32 samples with
//     uniform-broadcast LDS + FFMA2, scatters results to the ping-pong buffer.
//  4) k_epi: per-batch-row CTA folds W7(d7) @ (payload @ SH) and finishes.
//
//  R9 fix: gather loop now strides r += 64 to cover ALL 128 tile rows
//  (R8 filled only rows 0..63 -> half the samples used garbage v).

#define NMAX  (1024 * 256)
#define RANK  64
#define TILE  128
#define VS    68          // smem v row stride in floats (272 B: 16B-aligned)

typedef unsigned long long u64;

__device__ float    g_vA[(size_t)NMAX * 64];
__device__ float    g_vB[(size_t)NMAX * 64];
__device__ float    g_w2[192 * 4096];      // packed combined weights
__device__ int      g_perm[3][NMAX];
__device__ unsigned g_dig[NMAX];
__device__ int      g_cnt[192];
__device__ int      g_cur[192];

__device__ __forceinline__ u64 pk2(float lo, float hi) {
    u64 r; asm("mov.b64 %0, {%1, %2};" : "=l"(r) : "f"(lo), "f"(hi)); return r;
}
__device__ __forceinline__ void upk2(u64 v, float& lo, float& hi) {
    asm("mov.b64 {%0, %1}, %2;" : "=f"(lo), "=f"(hi) : "l"(v));
}
__device__ __forceinline__ u64 ffma2(u64 a, u64 b, u64 c) {
    u64 d; asm("fma.rn.f32x2 %0, %1, %2, %3;" : "=l"(d) : "l"(a), "l"(b), "l"(c)); return d;
}
__device__ __forceinline__ u64 add2(u64 a, u64 b) {
    u64 d; asm("add.rn.f32x2 %0, %1, %2;" : "=l"(d) : "l"(a), "l"(b)); return d;
}

__device__ __forceinline__ unsigned compute_dig(float cx, float cy, float cz) {
    const int ix = min(255, max(0, (int)floorf((cx * 0.5f + 0.5f) * 256.f)));
    const int iy = min(255, max(0, (int)floorf((cy * 0.5f + 0.5f) * 256.f)));
    const int iz = min(255, max(0, (int)floorf((cz * 0.5f + 0.5f) * 256.f)));
    unsigned dig = 0;
#pragma unroll
    for (int l = 0; l < 8; ++l) {
        const int s = 7 - l;
        const unsigned d = (((ix >> s) & 1) << 2) | (((iy >> s) & 1) << 1) | ((iz >> s) & 1);
        dig |= d << (4 * l);
    }
    return dig;
}
__device__ __forceinline__ int pair_key(unsigned dg, int p) {
    return (int)(((dg >> (4 * (2 * p + 1))) & 7u) * 8u + ((dg >> (4 * (2 * p + 2))) & 7u));
}

// ---------------- sort pipeline ----------------
__global__ void k_zero() { if (threadIdx.x < 192) g_cnt[threadIdx.x] = 0; }

__global__ __launch_bounds__(256) void k_keys(const float* __restrict__ coords) {
    __shared__ int lc[192];
    const int t = threadIdx.x;
    if (t < 192) lc[t] = 0;
    __syncthreads();
    const int n = blockIdx.x * 256 + t;
    const unsigned dg = compute_dig(coords[3 * n], coords[3 * n + 1], coords[3 * n + 2]);
    g_dig[n] = dg;
#pragma unroll
    for (int p = 0; p < 3; ++p) atomicAdd(&lc[p * 64 + pair_key(dg, p)], 1);
    __syncthreads();
    if (t < 192 && lc[t]) atomicAdd(&g_cnt[t], lc[t]);
}

__global__ void k_scan() {
    const int t = threadIdx.x;
    if (t < 3) {
        int s = 0;
        for (int d = 0; d < 64; ++d) { g_cur[t * 64 + d] = s; s += g_cnt[t * 64 + d]; }
    }
}

__global__ __launch_bounds__(256) void k_scatter() {
    __shared__ int lc[192], lb[192], lp[192];
    const int t = threadIdx.x;
    if (t < 192) { lc[t] = 0; lp[t] = 0; }
    __syncthreads();
    const int n = blockIdx.x * 256 + t;
    const unsigned dg = g_dig[n];
    int key[3];
#pragma unroll
    for (int p = 0; p < 3; ++p) {
        key[p] = pair_key(dg, p);
        atomicAdd(&lc[p * 64 + key[p]], 1);
    }
    __syncthreads();
    if (t < 192 && lc[t]) lb[t] = atomicAdd(&g_cur[t], lc[t]);
    __syncthreads();
#pragma unroll
    for (int p = 0; p < 3; ++p) {
        const int r = atomicAdd(&lp[p * 64 + key[p]], 1);
        g_perm[p][lb[p * 64 + key[p]] + r] = n;
    }
}

// ---------------- precombine: packed pair-level weights ----------------
// C[r][s] = sum_k cores[2p][r][da][k] * cores[2p+1][k][db][s]
// Packed: float idx ((combo*32 + (r>>1))*32 + (s>>1))*4 + (s&1)*2 + (r&1)
__global__ void __launch_bounds__(128) precombine_kernel(const float* __restrict__ cores)
{
    __shared__ float sA[4096];
    __shared__ float sB[4096];
    const int combo = blockIdx.x;          // p*64 + da*8 + db
    const int p  = combo >> 6;
    const int da = (combo >> 3) & 7;
    const int db = combo & 7;
    const int t = threadIdx.x;

    const float* A  = cores + (size_t)(2 * p) * 32768 + da * 64;
    const float* Bm = cores + (size_t)(2 * p + 1) * 32768 + db * 64;
    for (int i = t; i < 1024; i += 128) {
        const int row = i >> 4, c4 = (i & 15) * 4;
        *(float4*)(sA + row * 64 + c4) = *(const float4*)(A  + row * 512 + c4);
        *(float4*)(sB + row * 64 + c4) = *(const float4*)(Bm + row * 512 + c4);
    }
    __syncthreads();

    const int r  = t >> 1;
    const int s0 = (t & 1) * 32;
    float acc[32];
#pragma unroll
    for (int i = 0; i < 32; ++i) acc[i] = 0.f;
#pragma unroll 4
    for (int k = 0; k < 64; ++k) {
        const float a = sA[r * 64 + k];
#pragma unroll
        for (int i = 0; i < 32; ++i) acc[i] = fmaf(a, sB[k * 64 + s0 + i], acc[i]);
    }
    const int q = r >> 1, pr = r & 1;
#pragma unroll
    for (int i = 0; i < 32; ++i) {
        const int j = s0 + i;
        g_w2[((size_t)(combo * 32 + q) * 32 + (j >> 1)) * 4 + (j & 1) * 2 + pr] = acc[i];
    }
}

// ---------------- streaming pass ----------------
__global__ __launch_bounds__(TILE, 3) void k_pass(int pass, const float* __restrict__ core0)
{
    __shared__ float vt[TILE * VS];
    __shared__ int   sids[TILE];
    __shared__ int   ridx[TILE];
    __shared__ int   keys[TILE];
    const int t = threadIdx.x, lane = t & 31, w = t >> 5;
    const int base = blockIdx.x * TILE;

    const float* vin = (pass == 0) ? core0 : ((pass == 1) ? g_vB : g_vA);
    float*       vout = (pass == 1) ? g_vA : g_vB;

    {
        const int sid = g_perm[pass][base + t];
        const unsigned dg = g_dig[sid];
        sids[t] = sid;
        keys[t] = pair_key(dg, pass);
        ridx[t] = (pass == 0) ? (int)(dg & 7u) : sid;
    }
    __syncthreads();

    // gather: 2 threads per row, interleaved 16B chunks; stride covers ALL rows
    {
        const int h = t & 1;
#pragma unroll
        for (int r = t >> 1; r < TILE; r += 64) {
            const float* srow = vin + (size_t)ridx[r] * 64;
            float* drow = vt + r * VS;
#pragma unroll
            for (int j = 0; j < 8; ++j) {
                const int c = 2 * j + h;
                *(float4*)(drow + c * 4) = *(const float4*)(srow + c * 4);
            }
        }
    }
    __syncthreads();

    // compute: warp w -> samples [32w, 32w+32), weights in registers
    u64 wa[32], wb[32];
    int cur = -1;
#pragma unroll 1
    for (int s = w * 32; s < w * 32 + 32; ++s) {
        const int key = keys[s];
        if (key != cur) {                 // ~once per pass (runs ~4096 long)
            cur = key;
            const ulonglong2* wp = (const ulonglong2*)g_w2
                                   + (size_t)(pass * 64 + key) * 1024 + lane;
#pragma unroll
            for (int k = 0; k < 32; ++k) {
                const ulonglong2 z = wp[k * 32];   // coalesced LDG.128
                wa[k] = z.x; wb[k] = z.y;
            }
        }
        const ulonglong2* vr = (const ulonglong2*)(vt + s * VS);
        u64 a0 = 0ull, a1 = 0ull, b0 = 0ull, b1 = 0ull;
#pragma unroll
        for (int q = 0; q < 16; ++q) {
            const ulonglong2 p = vr[q];            // uniform LDS.128 (broadcast)
            a0 = ffma2(wa[2 * q + 0], p.x, a0);
            b0 = ffma2(wb[2 * q + 0], p.x, b0);
            a1 = ffma2(wa[2 * q + 1], p.y, a1);
            b1 = ffma2(wb[2 * q + 1], p.y, b1);
        }
        float x0, x1, y0, y1;
        upk2(add2(a0, a1), x0, x1);
        upk2(add2(b0, b1), y0, y1);
        // scatter: warp writes one contiguous 256B row (STG.64 per lane)
        *(u64*)(vout + (size_t)sids[s] * 64 + 2 * lane) = pk2(x0 + x1, y0 + y1);
    }
}

// ---------------- epilogue: fold W7(d7) @ (payload @ SH) ----------------
__global__ __launch_bounds__(256) void k_epi(const float* __restrict__ coords,
                                             const float* __restrict__ viewdirs,
                                             const float* __restrict__ cores,
                                             const float* __restrict__ payload,
                                             float* __restrict__ out, int N)
{
    __shared__ float pp[256];        // P' : 64 x float4
    __shared__ float wps[8 * 260];   // WP[d][r][j]: d*260 + r*4 + j
    const int tid = threadIdx.x;
    const int b   = blockIdx.x;
    const int n   = b * 256 + tid;

    const float cx = coords[3 * n + 0];
    const float cy = coords[3 * n + 1];
    const float cz = coords[3 * n + 2];
    const float msk = (fabsf(cx) <= 1.f && fabsf(cy) <= 1.f && fabsf(cz) <= 1.f) ? 1.f : 0.f;
    const int d7 = (int)((g_dig[n] >> 28) & 7u);

    if (tid < RANK) {
        const float* vd = viewdirs + 3 * b;
        const float dx = vd[0], dy = vd[1], dz = vd[2];
        float shv[9];
        shv[0] = 0.28209479177387814f;
        shv[1] = -0.4886025119029199f * dy;
        shv[2] =  0.4886025119029199f * dz;
        shv[3] = -0.4886025119029199f * dx;
        shv[4] =  1.0925484305920792f * dx * dy;
        shv[5] = -1.0925484305920792f * dy * dz;
        shv[6] =  0.31539156525252005f * (2.f * dz * dz - dx * dx - dy * dy);
        shv[7] = -1.0925484305920792f * dx * dz;
        shv[8] =  0.5462742152960396f * (dx * dx - dy * dy);
        const float* pr = payload + tid * 28;
        float s0 = 0.f, s1 = 0.f, s2 = 0.f;
#pragma unroll
        for (int j = 0; j < 9; ++j) {
            s0 = fmaf(pr[j],      shv[j], s0);
            s1 = fmaf(pr[9 + j],  shv[j], s1);
            s2 = fmaf(pr[18 + j], shv[j], s2);
        }
        *(float4*)(pp + 4 * tid) = make_float4(s0, s1, s2, pr[27]);
    }
    __syncthreads();

    // WP[d] = W7(d) @ P'
#pragma unroll
    for (int i = 0; i < 2; ++i) {
        const int idx = tid + i * 256;
        const int d = idx >> 6, r = idx & 63;
        const float* src = cores + (size_t)6 * 32768 + r * 512 + d * 64;
        float a0 = 0.f, a1 = 0.f, a2 = 0.f, a3 = 0.f;
#pragma unroll 4
        for (int s4 = 0; s4 < 16; ++s4) {
            const float4 w4 = *(const float4*)(src + 4 * s4);
            const float4 p0 = *(const float4*)(pp + 4 * (4 * s4 + 0));
            const float4 p1 = *(const float4*)(pp + 4 * (4 * s4 + 1));
            const float4 p2 = *(const float4*)(pp + 4 * (4 * s4 + 2));
            const float4 p3 = *(const float4*)(pp + 4 * (4 * s4 + 3));
            a0 = fmaf(w4.x, p0.x, a0); a1 = fmaf(w4.x, p0.y, a1);
            a2 = fmaf(w4.x, p0.z, a2); a3 = fmaf(w4.x, p0.w, a3);
            a0 = fmaf(w4.y, p1.x, a0); a1 = fmaf(w4.y, p1.y, a1);
            a2 = fmaf(w4.y, p1.z, a2); a3 = fmaf(w4.y, p1.w, a3);
            a0 = fmaf(w4.z, p2.x, a0); a1 = fmaf(w4.z, p2.y, a1);
            a2 = fmaf(w4.z, p2.z, a2); a3 = fmaf(w4.z, p2.w, a3);
            a0 = fmaf(w4.w, p3.x, a0); a1 = fmaf(w4.w, p3.y, a1);
            a2 = fmaf(w4.w, p3.z, a2); a3 = fmaf(w4.w, p3.w, a3);
        }
        *(float4*)(wps + d * 260 + r * 4) = make_float4(a0, a1, a2, a3);
    }
    __syncthreads();

    // out = v6 @ WP[d7]  (v6 rows in g_vB, natural order -> coalesced)
    float o0 = 0.f, o1 = 0.f, o2 = 0.f, o3 = 0.f;
    {
        const float* vrowg = g_vB + (size_t)n * 64;
        const float* wrow = wps + d7 * 260;
#pragma unroll
        for (int q = 0; q < 16; ++q) {
            const float4 t = *(const float4*)(vrowg + 4 * q);
            const float4 p0 = *(const float4*)(wrow + 4 * (4 * q + 0));
            const float4 p1 = *(const float4*)(wrow + 4 * (4 * q + 1));
            const float4 p2 = *(const float4*)(wrow + 4 * (4 * q + 2));
            const float4 p3 = *(const float4*)(wrow + 4 * (4 * q + 3));
            o0 = fmaf(t.x, p0.x, o0); o1 = fmaf(t.x, p0.y, o1);
            o2 = fmaf(t.x, p0.z, o2); o3 = fmaf(t.x, p0.w, o3);
            o0 = fmaf(t.y, p1.x, o0); o1 = fmaf(t.y, p1.y, o1);
            o2 = fmaf(t.y, p1.z, o2); o3 = fmaf(t.y, p1.w, o3);
            o0 = fmaf(t.z, p2.x, o0); o1 = fmaf(t.z, p2.y, o1);
            o2 = fmaf(t.z, p2.z, o2); o3 = fmaf(t.z, p2.w, o3);
            o0 = fmaf(t.w, p3.x, o0); o1 = fmaf(t.w, p3.y, o1);
            o2 = fmaf(t.w, p3.z, o2); o3 = fmaf(t.w, p3.w, o3);
        }
    }
    out[3 * n + 0] = o0 * msk;
    out[3 * n + 1] = o1 * msk;
    out[3 * n + 2] = o2 * msk;
    out[3 * N + n] = o3 * msk;   // sigma block after rgb block
}

extern "C" void kernel_launch(void* const* d_in, const int* in_sizes, int n_in,
                              void* d_out, int out_size) {
    const float* coords   = (const float*)d_in[0];  // (B,R,3)
    const float* viewdirs = (const float*)d_in[1];  // (B,3)
    const float* core0    = (const float*)d_in[2];  // (1,8,64)
    const float* cores    = (const float*)d_in[3];  // (7,64,8,64)
    const float* payload  = (const float*)d_in[4];  // (64,28)

    const int N = in_sizes[0] / 3;   // 262144
    const int B = in_sizes[1] / 3;   // 1024

    k_zero<<<1, 192>>>();
    k_keys<<<N / 256, 256>>>(coords);
    k_scan<<<1, 32>>>();
    k_scatter<<<N / 256, 256>>>();
    precombine_kernel<<<192, 128>>>(cores);
    k_pass<<<N / TILE, TILE>>>(0, core0);
    k_pass<<<N / TILE, TILE>>>(1, core0);
    k_pass<<<N / TILE, TILE>>>(2, core0);
    k_epi<<<B, 256>>>(coords, viewdirs, cores, payload, (float*)d_out, N);
}